// round 1
// baseline (speedup 1.0000x reference)
#include <cuda_runtime.h>
#include <math.h>

// Problem shape (fixed for this problem instance)
#define T_TOK 1024
#define H_DIM 1024
#define E_NUM 8
#define I_DIM 1024
#define K_TOP 2
#define ALPHA 1.702f
#define LIMIT 7.0f

// ---------------- scratch (static device globals; no allocation) -------------
__device__ int   g_top_idx[T_TOK * 2];
__device__ float g_top_w[T_TOK * 2];
__device__ int   g_cnt[E_NUM];
__device__ int   g_tok[E_NUM][T_TOK];
__device__ float g_wt[E_NUM][T_TOK];
__device__ float g_act[(size_t)E_NUM * T_TOK * I_DIM];  // 32 MiB activation scratch

// ---------------- router: logits -> softmax -> top-2 ------------------------
// One block per token; 8 warps, warp e computes logit for expert e.
__global__ void router_k(const float* __restrict__ x,
                         const float* __restrict__ Wr,
                         const float* __restrict__ br) {
    int t = blockIdx.x;
    int lane = threadIdx.x & 31;
    int warp = threadIdx.x >> 5;

    const float* xr = x + (size_t)t * H_DIM;
    const float* wr = Wr + (size_t)warp * H_DIM;
    float s = 0.f;
#pragma unroll
    for (int h = lane * 4; h < H_DIM; h += 128) {
        float4 a = *(const float4*)(xr + h);
        float4 b = *(const float4*)(wr + h);
        s += a.x * b.x + a.y * b.y + a.z * b.z + a.w * b.w;
    }
#pragma unroll
    for (int o = 16; o; o >>= 1) s += __shfl_xor_sync(0xffffffffu, s, o);

    __shared__ float lg[E_NUM];
    if (lane == 0) lg[warp] = s + br[warp];
    __syncthreads();

    if (threadIdx.x == 0) {
        float mx = lg[0];
#pragma unroll
        for (int e = 1; e < E_NUM; e++) mx = fmaxf(mx, lg[e]);
        float ex[E_NUM];
        float sum = 0.f;
#pragma unroll
        for (int e = 0; e < E_NUM; e++) { ex[e] = expf(lg[e] - mx); sum += ex[e]; }
        // top-2 of logits == top-2 of softmax (monotone); strict '>' keeps
        // lowest index on ties, matching jax.lax.top_k.
        int i0 = 0;
#pragma unroll
        for (int e = 1; e < E_NUM; e++) if (lg[e] > lg[i0]) i0 = e;
        int i1 = (i0 == 0) ? 1 : 0;
#pragma unroll
        for (int e = 0; e < E_NUM; e++) if (e != i0 && lg[e] > lg[i1]) i1 = e;
        float inv = 1.f / sum;
        g_top_idx[2 * t + 0] = i0;
        g_top_idx[2 * t + 1] = i1;
        g_top_w[2 * t + 0] = ex[i0] * inv;
        g_top_w[2 * t + 1] = ex[i1] * inv;
    }
}

// ---------------- dispatch: deterministic per-expert token lists -------------
__global__ void dispatch_k() {
    int e = threadIdx.x;
    if (e >= E_NUM) return;
    int c = 0;
    for (int t = 0; t < T_TOK; t++) {
        int i0 = g_top_idx[2 * t + 0];
        int i1 = g_top_idx[2 * t + 1];
        if (i0 == e)      { g_tok[e][c] = t; g_wt[e][c] = g_top_w[2 * t + 0]; c++; }
        else if (i1 == e) { g_tok[e][c] = t; g_wt[e][c] = g_top_w[2 * t + 1]; c++; }
    }
    g_cnt[e] = c;
}

// ---------------- gate_up grouped GEMM + clamped-GLU epilogue ---------------
// grid: (I/64, T/64, E). 64x64 output tile of act[e]; gate & up accumulated
// simultaneously (two B tiles), so the GLU epilogue is local.
__global__ void __launch_bounds__(256) gateup_k(const float* __restrict__ x,
                                                const float* __restrict__ W1,
                                                const float* __restrict__ b1) {
    int e = blockIdx.z;
    int cnt = g_cnt[e];
    int mB = blockIdx.y * 64;
    if (mB >= cnt) return;
    int nB = blockIdx.x * 64;

    __shared__ float As[16][64];
    __shared__ float Bg[16][64];
    __shared__ float Bu[16][64];
    __shared__ int toks[64];

    int tid = threadIdx.x;
    if (tid < 64) toks[tid] = (mB + tid < cnt) ? g_tok[e][mB + tid] : -1;
    __syncthreads();

    int tx = tid & 15, ty = tid >> 4;
    float ag[4][4] = {}, au[4][4] = {};

    const float* W1e = W1 + (size_t)e * H_DIM * 2 * I_DIM;
    int lm = tid >> 2;           // A-load row within tile
    int lk = (tid & 3) * 4;      // A-load k offset (float4)
    int t_row = toks[lm];
    int bk = tid >> 4;           // B-load k row
    int bn = (tid & 15) * 4;     // B-load col (float4)

    for (int k0 = 0; k0 < H_DIM; k0 += 16) {
        float4 av = make_float4(0.f, 0.f, 0.f, 0.f);
        if (t_row >= 0) av = *(const float4*)(x + (size_t)t_row * H_DIM + k0 + lk);
        As[lk + 0][lm] = av.x; As[lk + 1][lm] = av.y;
        As[lk + 2][lm] = av.z; As[lk + 3][lm] = av.w;

        const float* wrow = W1e + (size_t)(k0 + bk) * (2 * I_DIM) + nB + bn;
        *(float4*)&Bg[bk][bn] = *(const float4*)(wrow);
        *(float4*)&Bu[bk][bn] = *(const float4*)(wrow + I_DIM);
        __syncthreads();

#pragma unroll
        for (int k = 0; k < 16; k++) {
            float4 a  = *(const float4*)&As[k][ty * 4];
            float4 bg = *(const float4*)&Bg[k][tx * 4];
            float4 bu = *(const float4*)&Bu[k][tx * 4];
            float aa[4] = {a.x, a.y, a.z, a.w};
            float gg[4] = {bg.x, bg.y, bg.z, bg.w};
            float uu[4] = {bu.x, bu.y, bu.z, bu.w};
#pragma unroll
            for (int i2 = 0; i2 < 4; i2++)
#pragma unroll
                for (int j = 0; j < 4; j++) {
                    ag[i2][j] += aa[i2] * gg[j];
                    au[i2][j] += aa[i2] * uu[j];
                }
        }
        __syncthreads();
    }

    float* actBase = g_act + ((size_t)e * T_TOK + mB) * I_DIM;
#pragma unroll
    for (int i2 = 0; i2 < 4; i2++) {
        int m = ty * 4 + i2;
        if (mB + m >= cnt) continue;
#pragma unroll
        for (int j = 0; j < 4; j++) {
            int n = nB + tx * 4 + j;
            float g = ag[i2][j] + b1[e * 2 * I_DIM + n];
            float u = au[i2][j] + b1[e * 2 * I_DIM + I_DIM + n];
            g = fminf(g, LIMIT);                      // gate: upper clamp only
            u = fminf(fmaxf(u, -LIMIT), LIMIT);       // up: both sides
            float glu = g / (1.f + expf(-ALPHA * g)); // g * sigmoid(alpha*g)
            actBase[(size_t)m * I_DIM + n] = (u + 1.f) * glu;
        }
    }
}

// ---------------- down grouped GEMM + weighted atomic combine ---------------
__global__ void __launch_bounds__(256) down_k(const float* __restrict__ W2,
                                              const float* __restrict__ b2,
                                              float* __restrict__ out) {
    int e = blockIdx.z;
    int cnt = g_cnt[e];
    int mB = blockIdx.y * 64;
    if (mB >= cnt) return;
    int nB = blockIdx.x * 64;

    __shared__ float As[16][64];
    __shared__ float Bs[16][64];
    __shared__ int toks[64];
    __shared__ float wts[64];

    int tid = threadIdx.x;
    if (tid < 64) {
        int ok = (mB + tid < cnt);
        toks[tid] = ok ? g_tok[e][mB + tid] : -1;
        wts[tid]  = ok ? g_wt[e][mB + tid] : 0.f;
    }
    __syncthreads();

    int tx = tid & 15, ty = tid >> 4;
    float acc[4][4] = {};

    const float* Ae  = g_act + (size_t)e * T_TOK * I_DIM;
    const float* W2e = W2 + (size_t)e * I_DIM * H_DIM;
    int lm = tid >> 2;
    int lk = (tid & 3) * 4;
    int bk = tid >> 4;
    int bn = (tid & 15) * 4;
    bool arow_ok = (mB + lm < cnt);

    for (int k0 = 0; k0 < I_DIM; k0 += 16) {
        float4 av = make_float4(0.f, 0.f, 0.f, 0.f);
        if (arow_ok) av = *(const float4*)(Ae + (size_t)(mB + lm) * I_DIM + k0 + lk);
        As[lk + 0][lm] = av.x; As[lk + 1][lm] = av.y;
        As[lk + 2][lm] = av.z; As[lk + 3][lm] = av.w;

        *(float4*)&Bs[bk][bn] =
            *(const float4*)(W2e + (size_t)(k0 + bk) * H_DIM + nB + bn);
        __syncthreads();

#pragma unroll
        for (int k = 0; k < 16; k++) {
            float4 a = *(const float4*)&As[k][ty * 4];
            float4 b = *(const float4*)&Bs[k][tx * 4];
            float aa[4] = {a.x, a.y, a.z, a.w};
            float bb[4] = {b.x, b.y, b.z, b.w};
#pragma unroll
            for (int i2 = 0; i2 < 4; i2++)
#pragma unroll
                for (int j = 0; j < 4; j++)
                    acc[i2][j] += aa[i2] * bb[j];
        }
        __syncthreads();
    }

#pragma unroll
    for (int i2 = 0; i2 < 4; i2++) {
        int m = ty * 4 + i2;
        if (mB + m >= cnt) continue;
        int t = toks[m];
        float w = wts[m];
#pragma unroll
        for (int j = 0; j < 4; j++) {
            int n = nB + tx * 4 + j;
            float v = w * (acc[i2][j] + b2[e * H_DIM + n]);
            atomicAdd(out + (size_t)t * H_DIM + n, v);
        }
    }
}

// ---------------- launcher ---------------------------------------------------
extern "C" void kernel_launch(void* const* d_in, const int* in_sizes, int n_in,
                              void* d_out, int out_size) {
    const float* x  = (const float*)d_in[0];  // hidden_states [1,1024,1024]
    const float* Wr = (const float*)d_in[1];  // router_weight [8,1024]
    const float* br = (const float*)d_in[2];  // router_bias [8]
    const float* W1 = (const float*)d_in[3];  // gate_up_proj [8,1024,2048]
    const float* b1 = (const float*)d_in[4];  // gate_up_bias [8,2048]
    const float* W2 = (const float*)d_in[5];  // down_proj [8,1024,1024]
    const float* b2 = (const float*)d_in[6];  // down_bias [8,1024]
    float* out = (float*)d_out;

    cudaMemsetAsync(out, 0, (size_t)out_size * sizeof(float), 0);
    router_k<<<T_TOK, 256>>>(x, Wr, br);
    dispatch_k<<<1, 32>>>();
    gateup_k<<<dim3(I_DIM / 64, T_TOK / 64, E_NUM), 256>>>(x, W1, b1);
    down_k<<<dim3(H_DIM / 64, T_TOK / 64, E_NUM), 256>>>(W2, b2, out);
}

// round 8
// speedup vs baseline: 1.1361x; 1.1361x over previous
#include <cuda_runtime.h>
#include <cuda_bf16.h>
#include <math.h>
#include <stdint.h>

#define T_TOK 1024
#define H_DIM 1024
#define E_NUM 8
#define I_DIM 1024
#define ALPHA 1.702f
#define LIMIT 7.0f

// ---------------- scratch (identical footprint to the PASSING Round-1 run) ---
__device__ int   g_top_idx[T_TOK * 2];
__device__ float g_top_w[T_TOK * 2];
__device__ int   g_cnt[E_NUM];
__device__ int   g_tok[E_NUM][T_TOK];
__device__ float g_wt[E_NUM][T_TOK];
__device__ __align__(256) float g_act[(size_t)E_NUM * T_TOK * I_DIM];  // 32 MiB

// ---------------- mma.sync + split helpers -----------------------------------
__device__ __forceinline__ void mma16816(float c[4], const uint32_t a[4],
                                         const uint32_t b[2]) {
    asm volatile(
        "mma.sync.aligned.m16n8k16.row.col.f32.bf16.bf16.f32 "
        "{%0,%1,%2,%3}, {%4,%5,%6,%7}, {%8,%9}, {%0,%1,%2,%3};"
        : "+f"(c[0]), "+f"(c[1]), "+f"(c[2]), "+f"(c[3])
        : "r"(a[0]), "r"(a[1]), "r"(a[2]), "r"(a[3]), "r"(b[0]), "r"(b[1]));
}
__device__ __forceinline__ uint32_t bfpack(__nv_bfloat16 a, __nv_bfloat16 b) {
    __nv_bfloat162 t = __halves2bfloat162(a, b);
    return *reinterpret_cast<uint32_t*>(&t);
}
// fp32 pair -> packed bf16 hi pair + packed bf16 lo (residual) pair
__device__ __forceinline__ void split2(float f0, float f1,
                                       uint32_t& hi, uint32_t& lo) {
    __nv_bfloat16 h0 = __float2bfloat16(f0);
    __nv_bfloat16 h1 = __float2bfloat16(f1);
    hi = bfpack(h0, h1);
    lo = bfpack(__float2bfloat16(f0 - __bfloat162float(h0)),
                __float2bfloat16(f1 - __bfloat162float(h1)));
}

// bf16 smem tiles, stride 40 elems/row: frag-load bank = (g*20+tig+c) mod 32,
// a perfect permutation over the warp -> conflict-free LDS.32.
__device__ __forceinline__ void ldsa(const __nv_bfloat16* base, int row, int col,
                                     uint32_t f[4]) {
    f[0] = *(const uint32_t*)(base + row * 40 + col);
    f[1] = *(const uint32_t*)(base + (row + 8) * 40 + col);
    f[2] = *(const uint32_t*)(base + row * 40 + col + 8);
    f[3] = *(const uint32_t*)(base + (row + 8) * 40 + col + 8);
}
__device__ __forceinline__ void ldsb(const __nv_bfloat16* base, int row, int col,
                                     uint32_t f[2]) {
    f[0] = *(const uint32_t*)(base + row * 40 + col);
    f[1] = *(const uint32_t*)(base + row * 40 + col + 8);
}

// ---------------- router (verbatim from passing Round 1) ---------------------
__global__ void router_k(const float* __restrict__ x,
                         const float* __restrict__ Wr,
                         const float* __restrict__ br) {
    int t = blockIdx.x;
    int lane = threadIdx.x & 31;
    int warp = threadIdx.x >> 5;
    const float* xr = x + (size_t)t * H_DIM;
    const float* wr = Wr + (size_t)warp * H_DIM;
    float s = 0.f;
#pragma unroll
    for (int h = lane * 4; h < H_DIM; h += 128) {
        float4 a = *(const float4*)(xr + h);
        float4 b = *(const float4*)(wr + h);
        s += a.x * b.x + a.y * b.y + a.z * b.z + a.w * b.w;
    }
#pragma unroll
    for (int o = 16; o; o >>= 1) s += __shfl_xor_sync(0xffffffffu, s, o);
    __shared__ float lg[E_NUM];
    if (lane == 0) lg[warp] = s + br[warp];
    __syncthreads();
    if (threadIdx.x == 0) {
        float mx = lg[0];
#pragma unroll
        for (int e = 1; e < E_NUM; e++) mx = fmaxf(mx, lg[e]);
        float ex[E_NUM], sum = 0.f;
#pragma unroll
        for (int e = 0; e < E_NUM; e++) { ex[e] = expf(lg[e] - mx); sum += ex[e]; }
        int i0 = 0;
#pragma unroll
        for (int e = 1; e < E_NUM; e++) if (lg[e] > lg[i0]) i0 = e;
        int i1 = (i0 == 0) ? 1 : 0;
#pragma unroll
        for (int e = 0; e < E_NUM; e++) if (e != i0 && lg[e] > lg[i1]) i1 = e;
        float inv = 1.f / sum;
        g_top_idx[2 * t + 0] = i0;  g_top_idx[2 * t + 1] = i1;
        g_top_w[2 * t + 0] = ex[i0] * inv;  g_top_w[2 * t + 1] = ex[i1] * inv;
    }
}

// ---------------- dispatch (serial, verbatim from passing Round 1) -----------
__global__ void dispatch_k() {
    int e = threadIdx.x;
    if (e >= E_NUM) return;
    int c = 0;
    for (int t = 0; t < T_TOK; t++) {
        int i0 = g_top_idx[2 * t + 0];
        int i1 = g_top_idx[2 * t + 1];
        if (i0 == e)      { g_tok[e][c] = t; g_wt[e][c] = g_top_w[2 * t + 0]; c++; }
        else if (i1 == e) { g_tok[e][c] = t; g_wt[e][c] = g_top_w[2 * t + 1]; c++; }
    }
    g_cnt[e] = c;
}

// ---------------- GEMM1 (mma): act = GLU(x_e @ W1_e + b1_e) ------------------
// CTA tile: 64 tokens x (128 gate cols + matching 128 up cols), BK=32.
// A: gathered token rows, split-bf16 at smem store.
// B: fp32 in smem (transposed [n][k], stride 35), split per-fragment.
__global__ void __launch_bounds__(256) gemm1_mma(const float* __restrict__ x,
                                                 const float* __restrict__ W1,
                                                 const float* __restrict__ b1) {
    int e = blockIdx.z;
    int cnt = g_cnt[e];
    int mB = blockIdx.y * 64;
    if (mB >= cnt) return;
    int nB = blockIdx.x * 128;

    __shared__ __align__(16) __nv_bfloat16 sAh[64 * 40];
    __shared__ __align__(16) __nv_bfloat16 sAl[64 * 40];
    __shared__ float sB[256 * 35];   // rows 0..127 gate, 128..255 up
    __shared__ int toks[64];

    int tid = threadIdx.x, lane = tid & 31, wid = tid >> 5;
    int wm = wid >> 2, wn = wid & 3, g = lane >> 2, tig = lane & 3;

    if (tid < 64) toks[tid] = (mB + tid < cnt) ? g_tok[e][mB + tid] : -1;
    __syncthreads();

    const float* W1e = W1 + (size_t)e * H_DIM * 2 * I_DIM;
    int lrA = tid >> 2, lcA = (tid & 3) * 8;
    int t_row = toks[lrA];
    int rB = tid >> 3, cB = (tid & 7) * 16;

    float acc[2][8][4];
#pragma unroll
    for (int a_ = 0; a_ < 2; a_++)
#pragma unroll
        for (int b_ = 0; b_ < 8; b_++)
#pragma unroll
            for (int k_ = 0; k_ < 4; k_++) acc[a_][b_][k_] = 0.f;

    for (int c = 0; c < H_DIM / 32; c++) {
        int k0 = c * 32;
        // A: 64x32 fp32 gather -> split-bf16 packed stores
        float4 v0 = make_float4(0.f, 0.f, 0.f, 0.f), v1 = v0;
        if (t_row >= 0) {
            const float* xp = x + (size_t)t_row * H_DIM + k0 + lcA;
            v0 = *(const float4*)xp;
            v1 = *(const float4*)(xp + 4);
        }
        uint4 h4, l4;
        split2(v0.x, v0.y, h4.x, l4.x);
        split2(v0.z, v0.w, h4.y, l4.y);
        split2(v1.x, v1.y, h4.z, l4.z);
        split2(v1.z, v1.w, h4.w, l4.w);
        *(uint4*)&sAh[lrA * 40 + lcA] = h4;
        *(uint4*)&sAl[lrA * 40 + lcA] = l4;
        // B: 32k x (128 gate + 128 up) fp32, stored transposed [n][k]
        const float* wrow = W1e + (size_t)(k0 + rB) * (2 * I_DIM) + nB + cB;
#pragma unroll
        for (int j = 0; j < 4; j++) {
            float4 gv = *(const float4*)(wrow + j * 4);
            float4 uv = *(const float4*)(wrow + I_DIM + j * 4);
            int n0 = cB + j * 4;
            sB[(n0 + 0) * 35 + rB] = gv.x;
            sB[(n0 + 1) * 35 + rB] = gv.y;
            sB[(n0 + 2) * 35 + rB] = gv.z;
            sB[(n0 + 3) * 35 + rB] = gv.w;
            sB[(128 + n0 + 0) * 35 + rB] = uv.x;
            sB[(128 + n0 + 1) * 35 + rB] = uv.y;
            sB[(128 + n0 + 2) * 35 + rB] = uv.z;
            sB[(128 + n0 + 3) * 35 + rB] = uv.w;
        }
        __syncthreads();
#pragma unroll
        for (int s = 0; s < 2; s++) {
            int col = s * 16 + tig * 2;
            uint32_t ah[2][4], al[2][4];
#pragma unroll
            for (int mi = 0; mi < 2; mi++) {
                int r = wm * 32 + mi * 16 + g;
                ldsa(sAh, r, col, ah[mi]);
                ldsa(sAl, r, col, al[mi]);
            }
#pragma unroll
            for (int ni = 0; ni < 8; ni++) {
                int np = (ni < 4 ? wn * 32 + ni * 8
                                 : 128 + wn * 32 + (ni - 4) * 8) + g;
                const float* bp = &sB[np * 35 + col];
                uint32_t bh[2], bl[2];
                split2(bp[0], bp[1], bh[0], bl[0]);
                split2(bp[8], bp[9], bh[1], bl[1]);
#pragma unroll
                for (int mi = 0; mi < 2; mi++) {
                    mma16816(acc[mi][ni], ah[mi], bh);
                    mma16816(acc[mi][ni], al[mi], bh);
                    mma16816(acc[mi][ni], ah[mi], bl);
                }
            }
        }
        __syncthreads();
    }

    // fused GLU epilogue -> fp32 act
#pragma unroll
    for (int mi = 0; mi < 2; mi++) {
        int m0 = mB + wm * 32 + mi * 16 + g;
#pragma unroll
        for (int ni = 0; ni < 4; ni++) {
            int j = nB + wn * 32 + ni * 8 + tig * 2;
            float bg0 = b1[(size_t)e * 2 * I_DIM + j];
            float bg1 = b1[(size_t)e * 2 * I_DIM + j + 1];
            float bu0 = b1[(size_t)e * 2 * I_DIM + I_DIM + j];
            float bu1 = b1[(size_t)e * 2 * I_DIM + I_DIM + j + 1];
#pragma unroll
            for (int h = 0; h < 2; h++) {
                int m = m0 + h * 8;
                if (m >= cnt) continue;
                float gv0 = acc[mi][ni][h * 2 + 0] + bg0;
                float gv1 = acc[mi][ni][h * 2 + 1] + bg1;
                float uv0 = acc[mi][ni + 4][h * 2 + 0] + bu0;
                float uv1 = acc[mi][ni + 4][h * 2 + 1] + bu1;
                gv0 = fminf(gv0, LIMIT);
                gv1 = fminf(gv1, LIMIT);
                uv0 = fminf(fmaxf(uv0, -LIMIT), LIMIT);
                uv1 = fminf(fmaxf(uv1, -LIMIT), LIMIT);
                float a0 = (uv0 + 1.f) * (gv0 / (1.f + __expf(-ALPHA * gv0)));
                float a1 = (uv1 + 1.f) * (gv1 / (1.f + __expf(-ALPHA * gv1)));
                float* ap = g_act + ((size_t)e * T_TOK + m) * I_DIM + j;
                ap[0] = a0;
                ap[1] = a1;
            }
        }
    }
}

// ---------------- GEMM2 (mma): out += w * (act @ W2_e + b2_e) ----------------
// CTA tile 128x128, BK=32, both operands split-bf16 at smem store.
__global__ void __launch_bounds__(256) gemm2_mma(const float* __restrict__ W2,
                                                 const float* __restrict__ b2,
                                                 float* __restrict__ out) {
    int e = blockIdx.z;
    int cnt = g_cnt[e];
    int mB = blockIdx.y * 128;
    if (mB >= cnt) return;
    int nB = blockIdx.x * 128;

    __shared__ __align__(16) __nv_bfloat16 sAh[128 * 40];
    __shared__ __align__(16) __nv_bfloat16 sAl[128 * 40];
    __shared__ __align__(16) __nv_bfloat16 sBh[128 * 40];
    __shared__ __align__(16) __nv_bfloat16 sBl[128 * 40];
    __shared__ int toks[128];
    __shared__ float wts[128];

    int tid = threadIdx.x, lane = tid & 31, wid = tid >> 5;
    int wm = wid >> 2, wn = wid & 3, g = lane >> 2, tig = lane & 3;

    if (tid < 128) {
        int ok = (mB + tid < cnt);
        toks[tid] = ok ? g_tok[e][mB + tid] : 0;
        wts[tid]  = ok ? g_wt[e][mB + tid] : 0.f;
    }
    __syncthreads();

    const float* W2e = W2 + (size_t)e * I_DIM * H_DIM;
    const float* Ae  = g_act + (size_t)e * T_TOK * I_DIM;
    int lrA = tid >> 2, lcA = (tid & 3) * 8;
    int rB = tid >> 3, cB = (tid & 7) * 16;

    float acc[4][4][4];
#pragma unroll
    for (int a_ = 0; a_ < 4; a_++)
#pragma unroll
        for (int b_ = 0; b_ < 4; b_++)
#pragma unroll
            for (int k_ = 0; k_ < 4; k_++) acc[a_][b_][k_] = 0.f;

    for (int c = 0; c < I_DIM / 32; c++) {
        int k0 = c * 32;
        // A: 128x32 fp32 act -> split-bf16, two passes of 64 rows
#pragma unroll
        for (int p = 0; p < 2; p++) {
            int row = p * 64 + lrA;
            float4 v0 = make_float4(0.f, 0.f, 0.f, 0.f), v1 = v0;
            if (mB + row < cnt) {
                const float* ap = Ae + (size_t)(mB + row) * I_DIM + k0 + lcA;
                v0 = *(const float4*)ap;
                v1 = *(const float4*)(ap + 4);
            }
            uint4 h4, l4;
            split2(v0.x, v0.y, h4.x, l4.x);
            split2(v0.z, v0.w, h4.y, l4.y);
            split2(v1.x, v1.y, h4.z, l4.z);
            split2(v1.z, v1.w, h4.w, l4.w);
            *(uint4*)&sAh[row * 40 + lcA] = h4;
            *(uint4*)&sAl[row * 40 + lcA] = l4;
        }
        // B: 32k x 128n fp32 -> split-bf16, stored transposed [n][k]
        const float* wrow = W2e + (size_t)(k0 + rB) * H_DIM + nB + cB;
#pragma unroll
        for (int j = 0; j < 4; j++) {
            float4 wv = *(const float4*)(wrow + j * 4);
            float f[4] = {wv.x, wv.y, wv.z, wv.w};
#pragma unroll
            for (int u = 0; u < 4; u++) {
                int n = cB + j * 4 + u;
                __nv_bfloat16 h = __float2bfloat16(f[u]);
                sBh[n * 40 + rB] = h;
                sBl[n * 40 + rB] = __float2bfloat16(f[u] - __bfloat162float(h));
            }
        }
        __syncthreads();
#pragma unroll
        for (int s = 0; s < 2; s++) {
            int col = s * 16 + tig * 2;
            uint32_t ah[4][4], al[4][4], bh[4][2], bl[4][2];
#pragma unroll
            for (int mi = 0; mi < 4; mi++) {
                int r = wm * 64 + mi * 16 + g;
                ldsa(sAh, r, col, ah[mi]);
                ldsa(sAl, r, col, al[mi]);
            }
#pragma unroll
            for (int ni = 0; ni < 4; ni++) {
                int r = wn * 32 + ni * 8 + g;
                ldsb(sBh, r, col, bh[ni]);
                ldsb(sBl, r, col, bl[ni]);
            }
#pragma unroll
            for (int mi = 0; mi < 4; mi++)
#pragma unroll
                for (int ni = 0; ni < 4; ni++) {
                    mma16816(acc[mi][ni], ah[mi], bh[ni]);
                    mma16816(acc[mi][ni], al[mi], bh[ni]);
                    mma16816(acc[mi][ni], ah[mi], bl[ni]);
                }
        }
        __syncthreads();
    }

    // weighted combine epilogue
#pragma unroll
    for (int mi = 0; mi < 4; mi++) {
        int mr0 = wm * 64 + mi * 16 + g;
#pragma unroll
        for (int h = 0; h < 2; h++) {
            int mr = mr0 + h * 8;
            int m = mB + mr;
            if (m >= cnt) continue;
            int t = toks[mr];
            float w = wts[mr];
            float* op = out + (size_t)t * H_DIM;
#pragma unroll
            for (int ni = 0; ni < 4; ni++) {
                int n = nB + wn * 32 + ni * 8 + tig * 2;
                float bb0 = b2[(size_t)e * H_DIM + n];
                float bb1 = b2[(size_t)e * H_DIM + n + 1];
                atomicAdd(op + n,     w * (acc[mi][ni][h * 2 + 0] + bb0));
                atomicAdd(op + n + 1, w * (acc[mi][ni][h * 2 + 1] + bb1));
            }
        }
    }
}

// ---------------- launcher ---------------------------------------------------
extern "C" void kernel_launch(void* const* d_in, const int* in_sizes, int n_in,
                              void* d_out, int out_size) {
    const float* x  = (const float*)d_in[0];  // hidden_states [1,1024,1024]
    const float* Wr = (const float*)d_in[1];  // router_weight [8,1024]
    const float* br = (const float*)d_in[2];  // router_bias [8]
    const float* W1 = (const float*)d_in[3];  // gate_up_proj [8,1024,2048]
    const float* b1 = (const float*)d_in[4];  // gate_up_bias [8,2048]
    const float* W2 = (const float*)d_in[5];  // down_proj [8,1024,1024]
    const float* b2 = (const float*)d_in[6];  // down_bias [8,1024]
    float* out = (float*)d_out;

    cudaMemsetAsync(out, 0, (size_t)out_size * sizeof(float), 0);
    router_k<<<T_TOK, 256>>>(x, Wr, br);
    dispatch_k<<<1, 32>>>();
    gemm1_mma<<<dim3(I_DIM / 128, T_TOK / 64, E_NUM), 256>>>(x, W1, b1);
    gemm2_mma<<<dim3(H_DIM / 128, T_TOK / 128, E_NUM), 256>>>(W2, b2, out);
}

// round 9
// speedup vs baseline: 1.6012x; 1.4094x over previous
#include <cuda_runtime.h>
#include <cuda_bf16.h>
#include <math.h>
#include <stdint.h>

#define T_TOK 1024
#define H_DIM 1024
#define E_NUM 8
#define I_DIM 1024
#define ALPHA 1.702f
#define LIMIT 7.0f
#define BK 16
#define STR 24   // smem row stride (elems); g*12 mod 32 is a perfect permutation

// ---------------- scratch ----------------------------------------------------
__device__ int   g_top_idx[T_TOK * 2];
__device__ float g_top_w[T_TOK * 2];
__device__ int   g_cnt[E_NUM];
__device__ int   g_tok[E_NUM][T_TOK];
__device__ float g_wt[E_NUM][T_TOK];
__device__ __align__(256) float g_act[(size_t)E_NUM * T_TOK * I_DIM];  // 32 MiB

// ---------------- mma.sync + split helpers -----------------------------------
__device__ __forceinline__ void mma16816(float c[4], const uint32_t a[4],
                                         const uint32_t b[2]) {
    asm volatile(
        "mma.sync.aligned.m16n8k16.row.col.f32.bf16.bf16.f32 "
        "{%0,%1,%2,%3}, {%4,%5,%6,%7}, {%8,%9}, {%0,%1,%2,%3};"
        : "+f"(c[0]), "+f"(c[1]), "+f"(c[2]), "+f"(c[3])
        : "r"(a[0]), "r"(a[1]), "r"(a[2]), "r"(a[3]), "r"(b[0]), "r"(b[1]));
}
__device__ __forceinline__ uint32_t bfpack(__nv_bfloat16 a, __nv_bfloat16 b) {
    __nv_bfloat162 t = __halves2bfloat162(a, b);
    return *reinterpret_cast<uint32_t*>(&t);
}
__device__ __forceinline__ void split2(float f0, float f1,
                                       uint32_t& hi, uint32_t& lo) {
    __nv_bfloat16 h0 = __float2bfloat16(f0);
    __nv_bfloat16 h1 = __float2bfloat16(f1);
    hi = bfpack(h0, h1);
    lo = bfpack(__float2bfloat16(f0 - __bfloat162float(h0)),
                __float2bfloat16(f1 - __bfloat162float(h1)));
}
// A fragment (k16): regs at (g, 2tig), (g+8, 2tig), (g, 2tig+8), (g+8, 2tig+8)
__device__ __forceinline__ void ldsa(const __nv_bfloat16* base, int row, int col,
                                     uint32_t f[4]) {
    f[0] = *(const uint32_t*)(base + row * STR + col);
    f[1] = *(const uint32_t*)(base + (row + 8) * STR + col);
    f[2] = *(const uint32_t*)(base + row * STR + col + 8);
    f[3] = *(const uint32_t*)(base + (row + 8) * STR + col + 8);
}
__device__ __forceinline__ void ldsb(const __nv_bfloat16* base, int row, int col,
                                     uint32_t f[2]) {
    f[0] = *(const uint32_t*)(base + row * STR + col);
    f[1] = *(const uint32_t*)(base + row * STR + col + 8);
}

// ---------------- router (proven) --------------------------------------------
__global__ void router_k(const float* __restrict__ x,
                         const float* __restrict__ Wr,
                         const float* __restrict__ br) {
    int t = blockIdx.x;
    int lane = threadIdx.x & 31;
    int warp = threadIdx.x >> 5;
    const float* xr = x + (size_t)t * H_DIM;
    const float* wr = Wr + (size_t)warp * H_DIM;
    float s = 0.f;
#pragma unroll
    for (int h = lane * 4; h < H_DIM; h += 128) {
        float4 a = *(const float4*)(xr + h);
        float4 b = *(const float4*)(wr + h);
        s += a.x * b.x + a.y * b.y + a.z * b.z + a.w * b.w;
    }
#pragma unroll
    for (int o = 16; o; o >>= 1) s += __shfl_xor_sync(0xffffffffu, s, o);
    __shared__ float lg[E_NUM];
    if (lane == 0) lg[warp] = s + br[warp];
    __syncthreads();
    if (threadIdx.x == 0) {
        float mx = lg[0];
#pragma unroll
        for (int e = 1; e < E_NUM; e++) mx = fmaxf(mx, lg[e]);
        float ex[E_NUM], sum = 0.f;
#pragma unroll
        for (int e = 0; e < E_NUM; e++) { ex[e] = expf(lg[e] - mx); sum += ex[e]; }
        int i0 = 0;
#pragma unroll
        for (int e = 1; e < E_NUM; e++) if (lg[e] > lg[i0]) i0 = e;
        int i1 = (i0 == 0) ? 1 : 0;
#pragma unroll
        for (int e = 0; e < E_NUM; e++) if (e != i0 && lg[e] > lg[i1]) i1 = e;
        float inv = 1.f / sum;
        g_top_idx[2 * t + 0] = i0;  g_top_idx[2 * t + 1] = i1;
        g_top_w[2 * t + 0] = ex[i0] * inv;  g_top_w[2 * t + 1] = ex[i1] * inv;
    }
}

// ---------------- dispatch (serial, proven) ----------------------------------
__global__ void dispatch_k() {
    int e = threadIdx.x;
    if (e >= E_NUM) return;
    int c = 0;
    for (int t = 0; t < T_TOK; t++) {
        int i0 = g_top_idx[2 * t + 0];
        int i1 = g_top_idx[2 * t + 1];
        if (i0 == e)      { g_tok[e][c] = t; g_wt[e][c] = g_top_w[2 * t + 0]; c++; }
        else if (i1 == e) { g_tok[e][c] = t; g_wt[e][c] = g_top_w[2 * t + 1]; c++; }
    }
    g_cnt[e] = c;
}

// ---------------- GEMM1 (mma): act = GLU(x_e @ W1_e + b1_e) ------------------
// CTA tile: 64 tokens x (128 gate + paired 128 up), BK=16, reg-prefetch pipe.
// B loaded column-per-thread (coalesced LDG.32), split once, STS.128 rows.
__global__ void __launch_bounds__(256) gemm1_mma(const float* __restrict__ x,
                                                 const float* __restrict__ W1,
                                                 const float* __restrict__ b1) {
    int e = blockIdx.z;
    int cnt = g_cnt[e];
    int mB = blockIdx.y * 64;
    if (mB >= cnt) return;
    int nB = blockIdx.x * 128;

    __shared__ __align__(16) __nv_bfloat16 sAh[64 * STR];
    __shared__ __align__(16) __nv_bfloat16 sAl[64 * STR];
    __shared__ __align__(16) __nv_bfloat16 sBh[256 * STR];
    __shared__ __align__(16) __nv_bfloat16 sBl[256 * STR];
    __shared__ int toks[64];

    int tid = threadIdx.x, lane = tid & 31, wid = tid >> 5;
    int wm = wid >> 2, wn = wid & 3, g = lane >> 2, tig = lane & 3;

    if (tid < 64) toks[tid] = (mB + tid < cnt) ? g_tok[e][mB + tid] : -1;
    __syncthreads();

    const float* W1e = W1 + (size_t)e * H_DIM * 2 * I_DIM;
    // A: thread -> (row, 4 cols)
    int arow = tid >> 2, acol = (tid & 3) * 4;
    int t_row = toks[arow];
    const float* aptr = (t_row >= 0) ? x + (size_t)t_row * H_DIM + acol : x;
    // B: thread -> one column n (0..127 gate, 128..255 up)
    const float* bcol = W1e + nB + (tid < 128 ? tid : (tid - 128) + I_DIM);

    float aReg[4], bReg[BK];
    float acc[2][8][4];
#pragma unroll
    for (int a_ = 0; a_ < 2; a_++)
#pragma unroll
        for (int b_ = 0; b_ < 8; b_++)
#pragma unroll
            for (int k_ = 0; k_ < 4; k_++) acc[a_][b_][k_] = 0.f;

#define G1_LOAD(c) do {                                                         \
        int k0 = (c) * BK;                                                      \
        if (t_row >= 0) { float4 v = *(const float4*)(aptr + k0);               \
            aReg[0] = v.x; aReg[1] = v.y; aReg[2] = v.z; aReg[3] = v.w; }       \
        else { aReg[0] = aReg[1] = aReg[2] = aReg[3] = 0.f; }                   \
        _Pragma("unroll")                                                       \
        for (int k = 0; k < BK; k++)                                            \
            bReg[k] = bcol[(size_t)(k0 + k) * (2 * I_DIM)];                     \
    } while (0)

    G1_LOAD(0);
    for (int c = 0; c < H_DIM / BK; c++) {
        // store staged regs (split fp32 -> bf16 hi/lo)
        {
            uint32_t h0, l0, h1, l1;
            split2(aReg[0], aReg[1], h0, l0);
            split2(aReg[2], aReg[3], h1, l1);
            *(uint2*)&sAh[arow * STR + acol] = make_uint2(h0, h1);
            *(uint2*)&sAl[arow * STR + acol] = make_uint2(l0, l1);
            uint32_t hb[8], lb[8];
#pragma unroll
            for (int k = 0; k < 8; k++)
                split2(bReg[2 * k], bReg[2 * k + 1], hb[k], lb[k]);
            *(uint4*)&sBh[tid * STR + 0] = make_uint4(hb[0], hb[1], hb[2], hb[3]);
            *(uint4*)&sBh[tid * STR + 8] = make_uint4(hb[4], hb[5], hb[6], hb[7]);
            *(uint4*)&sBl[tid * STR + 0] = make_uint4(lb[0], lb[1], lb[2], lb[3]);
            *(uint4*)&sBl[tid * STR + 8] = make_uint4(lb[4], lb[5], lb[6], lb[7]);
        }
        __syncthreads();
        if (c + 1 < H_DIM / BK) G1_LOAD(c + 1);   // LDG latency hides under mma
        {
            int col = tig * 2;
            uint32_t ah[2][4], al[2][4];
#pragma unroll
            for (int mi = 0; mi < 2; mi++) {
                int r = wm * 32 + mi * 16 + g;
                ldsa(sAh, r, col, ah[mi]);
                ldsa(sAl, r, col, al[mi]);
            }
#pragma unroll
            for (int ni = 0; ni < 8; ni++) {
                int np = (ni < 4 ? wn * 32 + ni * 8
                                 : 128 + wn * 32 + (ni - 4) * 8) + g;
                uint32_t bh[2], bl[2];
                ldsb(sBh, np, col, bh);
                ldsb(sBl, np, col, bl);
#pragma unroll
                for (int mi = 0; mi < 2; mi++) {
                    mma16816(acc[mi][ni], ah[mi], bh);
                    mma16816(acc[mi][ni], al[mi], bh);
                    mma16816(acc[mi][ni], ah[mi], bl);
                }
            }
        }
        __syncthreads();
    }

    // fused GLU epilogue -> fp32 act (proven)
#pragma unroll
    for (int mi = 0; mi < 2; mi++) {
        int m0 = mB + wm * 32 + mi * 16 + g;
#pragma unroll
        for (int ni = 0; ni < 4; ni++) {
            int j = nB + wn * 32 + ni * 8 + tig * 2;
            float bg0 = b1[(size_t)e * 2 * I_DIM + j];
            float bg1 = b1[(size_t)e * 2 * I_DIM + j + 1];
            float bu0 = b1[(size_t)e * 2 * I_DIM + I_DIM + j];
            float bu1 = b1[(size_t)e * 2 * I_DIM + I_DIM + j + 1];
#pragma unroll
            for (int h = 0; h < 2; h++) {
                int m = m0 + h * 8;
                if (m >= cnt) continue;
                float gv0 = acc[mi][ni][h * 2 + 0] + bg0;
                float gv1 = acc[mi][ni][h * 2 + 1] + bg1;
                float uv0 = acc[mi][ni + 4][h * 2 + 0] + bu0;
                float uv1 = acc[mi][ni + 4][h * 2 + 1] + bu1;
                gv0 = fminf(gv0, LIMIT);
                gv1 = fminf(gv1, LIMIT);
                uv0 = fminf(fmaxf(uv0, -LIMIT), LIMIT);
                uv1 = fminf(fmaxf(uv1, -LIMIT), LIMIT);
                float a0 = (uv0 + 1.f) * (gv0 / (1.f + __expf(-ALPHA * gv0)));
                float a1 = (uv1 + 1.f) * (gv1 / (1.f + __expf(-ALPHA * gv1)));
                float* ap = g_act + ((size_t)e * T_TOK + m) * I_DIM + j;
                ap[0] = a0;
                ap[1] = a1;
            }
        }
    }
}

// ---------------- GEMM2 (mma): out += w * (act @ W2_e + b2_e) ----------------
// CTA tile 128x128, BK=16, reg-prefetch pipe, column-per-thread B.
__global__ void __launch_bounds__(256) gemm2_mma(const float* __restrict__ W2,
                                                 const float* __restrict__ b2,
                                                 float* __restrict__ out) {
    int e = blockIdx.z;
    int cnt = g_cnt[e];
    int mB = blockIdx.y * 128;
    if (mB >= cnt) return;
    int nB = blockIdx.x * 128;

    __shared__ __align__(16) __nv_bfloat16 sAh[128 * STR];
    __shared__ __align__(16) __nv_bfloat16 sAl[128 * STR];
    __shared__ __align__(16) __nv_bfloat16 sBh[128 * STR];
    __shared__ __align__(16) __nv_bfloat16 sBl[128 * STR];
    __shared__ int toks[128];
    __shared__ float wts[128];

    int tid = threadIdx.x, lane = tid & 31, wid = tid >> 5;
    int wm = wid >> 2, wn = wid & 3, g = lane >> 2, tig = lane & 3;

    if (tid < 128) {
        int ok = (mB + tid < cnt);
        toks[tid] = ok ? g_tok[e][mB + tid] : 0;
        wts[tid]  = ok ? g_wt[e][mB + tid] : 0.f;
    }
    __syncthreads();

    const float* W2e = W2 + (size_t)e * I_DIM * H_DIM;
    const float* Ae  = g_act + (size_t)e * T_TOK * I_DIM;
    // A: thread -> (row, 8 cols)
    int arow = tid >> 1, acol = (tid & 1) * 8;
    bool aok = (mB + arow) < cnt;
    const float* aptr = Ae + (size_t)(mB + arow) * I_DIM + acol;
    // B: thread -> (column n, 8 k-rows)
    int bn = tid & 127, bkh = (tid >> 7) * 8;
    const float* bcol = W2e + nB + bn;

    float aReg[8], bReg[8];
    float acc[4][4][4];
#pragma unroll
    for (int a_ = 0; a_ < 4; a_++)
#pragma unroll
        for (int b_ = 0; b_ < 4; b_++)
#pragma unroll
            for (int k_ = 0; k_ < 4; k_++) acc[a_][b_][k_] = 0.f;

#define G2_LOAD(c) do {                                                         \
        int k0 = (c) * BK;                                                      \
        if (aok) {                                                              \
            float4 v0 = *(const float4*)(aptr + k0);                            \
            float4 v1 = *(const float4*)(aptr + k0 + 4);                        \
            aReg[0] = v0.x; aReg[1] = v0.y; aReg[2] = v0.z; aReg[3] = v0.w;     \
            aReg[4] = v1.x; aReg[5] = v1.y; aReg[6] = v1.z; aReg[7] = v1.w;     \
        } else {                                                                \
            _Pragma("unroll") for (int i = 0; i < 8; i++) aReg[i] = 0.f;        \
        }                                                                       \
        _Pragma("unroll")                                                       \
        for (int k = 0; k < 8; k++)                                             \
            bReg[k] = bcol[(size_t)(k0 + bkh + k) * H_DIM];                     \
    } while (0)

    G2_LOAD(0);
    for (int c = 0; c < I_DIM / BK; c++) {
        {
            uint32_t ha[4], la[4];
#pragma unroll
            for (int k = 0; k < 4; k++)
                split2(aReg[2 * k], aReg[2 * k + 1], ha[k], la[k]);
            *(uint4*)&sAh[arow * STR + acol] = make_uint4(ha[0], ha[1], ha[2], ha[3]);
            *(uint4*)&sAl[arow * STR + acol] = make_uint4(la[0], la[1], la[2], la[3]);
            uint32_t hb[4], lb[4];
#pragma unroll
            for (int k = 0; k < 4; k++)
                split2(bReg[2 * k], bReg[2 * k + 1], hb[k], lb[k]);
            *(uint4*)&sBh[bn * STR + bkh] = make_uint4(hb[0], hb[1], hb[2], hb[3]);
            *(uint4*)&sBl[bn * STR + bkh] = make_uint4(lb[0], lb[1], lb[2], lb[3]);
        }
        __syncthreads();
        if (c + 1 < I_DIM / BK) G2_LOAD(c + 1);
        {
            int col = tig * 2;
            uint32_t ah[4][4], al[4][4], bh[4][2], bl[4][2];
#pragma unroll
            for (int mi = 0; mi < 4; mi++) {
                int r = wm * 64 + mi * 16 + g;
                ldsa(sAh, r, col, ah[mi]);
                ldsa(sAl, r, col, al[mi]);
            }
#pragma unroll
            for (int ni = 0; ni < 4; ni++) {
                int r = wn * 32 + ni * 8 + g;
                ldsb(sBh, r, col, bh[ni]);
                ldsb(sBl, r, col, bl[ni]);
            }
#pragma unroll
            for (int mi = 0; mi < 4; mi++)
#pragma unroll
                for (int ni = 0; ni < 4; ni++) {
                    mma16816(acc[mi][ni], ah[mi], bh[ni]);
                    mma16816(acc[mi][ni], al[mi], bh[ni]);
                    mma16816(acc[mi][ni], ah[mi], bl[ni]);
                }
        }
        __syncthreads();
    }

    // weighted combine epilogue (proven)
#pragma unroll
    for (int mi = 0; mi < 4; mi++) {
        int mr0 = wm * 64 + mi * 16 + g;
#pragma unroll
        for (int h = 0; h < 2; h++) {
            int mr = mr0 + h * 8;
            int m = mB + mr;
            if (m >= cnt) continue;
            int t = toks[mr];
            float w = wts[mr];
            float* op = out + (size_t)t * H_DIM;
#pragma unroll
            for (int ni = 0; ni < 4; ni++) {
                int n = nB + wn * 32 + ni * 8 + tig * 2;
                float bb0 = b2[(size_t)e * H_DIM + n];
                float bb1 = b2[(size_t)e * H_DIM + n + 1];
                atomicAdd(op + n,     w * (acc[mi][ni][h * 2 + 0] + bb0));
                atomicAdd(op + n + 1, w * (acc[mi][ni][h * 2 + 1] + bb1));
            }
        }
    }
}

// ---------------- launcher ---------------------------------------------------
extern "C" void kernel_launch(void* const* d_in, const int* in_sizes, int n_in,
                              void* d_out, int out_size) {
    const float* x  = (const float*)d_in[0];
    const float* Wr = (const float*)d_in[1];
    const float* br = (const float*)d_in[2];
    const float* W1 = (const float*)d_in[3];
    const float* b1 = (const float*)d_in[4];
    const float* W2 = (const float*)d_in[5];
    const float* b2 = (const float*)d_in[6];
    float* out = (float*)d_out;

    cudaMemsetAsync(out, 0, (size_t)out_size * sizeof(float), 0);
    router_k<<<T_TOK, 256>>>(x, Wr, br);
    dispatch_k<<<1, 32>>>();
    gemm1_mma<<<dim3(I_DIM / 128, T_TOK / 64, E_NUM), 256>>>(x, W1, b1);
    gemm2_mma<<<dim3(H_DIM / 128, T_TOK / 128, E_NUM), 256>>>(W2, b2, out);
}

// round 10
// speedup vs baseline: 1.6358x; 1.0216x over previous
#include <cuda_runtime.h>
#include <cuda_bf16.h>
#include <math.h>
#include <stdint.h>

#define T_TOK 1024
#define H_DIM 1024
#define E_NUM 8
#define I_DIM 1024
#define ALPHA 1.702f
#define LIMIT 7.0f
#define BK 16
#define STR 24   // smem row stride (elems); conflict-free for LDS.32 and ldmatrix

// ---------------- scratch ----------------------------------------------------
__device__ int   g_top_idx[T_TOK * 2];
__device__ float g_top_w[T_TOK * 2];
__device__ int   g_cnt[E_NUM];
__device__ int   g_tok[E_NUM][T_TOK];
__device__ float g_wt[E_NUM][T_TOK];
__device__ __align__(256) float g_act[(size_t)E_NUM * T_TOK * I_DIM];  // 32 MiB

// ---------------- mma.sync / ldmatrix / split helpers ------------------------
__device__ __forceinline__ void mma16816(float c[4], const uint32_t a[4],
                                         const uint32_t b[2]) {
    asm volatile(
        "mma.sync.aligned.m16n8k16.row.col.f32.bf16.bf16.f32 "
        "{%0,%1,%2,%3}, {%4,%5,%6,%7}, {%8,%9}, {%0,%1,%2,%3};"
        : "+f"(c[0]), "+f"(c[1]), "+f"(c[2]), "+f"(c[3])
        : "r"(a[0]), "r"(a[1]), "r"(a[2]), "r"(a[3]), "r"(b[0]), "r"(b[1]));
}
__device__ __forceinline__ void ldsm4(uint32_t f[4], uint32_t addr) {
    asm volatile(
        "ldmatrix.sync.aligned.m8n8.x4.shared.b16 {%0,%1,%2,%3}, [%4];"
        : "=r"(f[0]), "=r"(f[1]), "=r"(f[2]), "=r"(f[3]) : "r"(addr));
}
__device__ __forceinline__ uint32_t bfpack(__nv_bfloat16 a, __nv_bfloat16 b) {
    __nv_bfloat162 t = __halves2bfloat162(a, b);
    return *reinterpret_cast<uint32_t*>(&t);
}
__device__ __forceinline__ void split2(float f0, float f1,
                                       uint32_t& hi, uint32_t& lo) {
    __nv_bfloat16 h0 = __float2bfloat16(f0);
    __nv_bfloat16 h1 = __float2bfloat16(f1);
    hi = bfpack(h0, h1);
    lo = bfpack(__float2bfloat16(f0 - __bfloat162float(h0)),
                __float2bfloat16(f1 - __bfloat162float(h1)));
}

// ldmatrix per-lane element offsets within a 16x16 (A) / 16(n)x16(k) (B) tile.
// A x4 -> a0=(r,k0) a1=(r+8,k0) a2=(r,k8) a3=(r+8,k8)
// B x4 -> {b[n-blk0][k0], b[n-blk0][k8], b[n-blk8][k0], b[n-blk8][k8]}
__device__ __forceinline__ int aoff_lane(int lane) {
    return ((lane & 7) + ((lane >> 3) & 1) * 8) * STR + ((lane >> 4) & 1) * 8;
}
__device__ __forceinline__ int boff_lane(int lane) {
    return (lane & 7) * STR + ((lane >> 3) & 1) * 8 + ((lane >> 4) & 1) * 8 * STR;
}

// ---------------- router (proven) --------------------------------------------
__global__ void router_k(const float* __restrict__ x,
                         const float* __restrict__ Wr,
                         const float* __restrict__ br) {
    int t = blockIdx.x;
    int lane = threadIdx.x & 31;
    int warp = threadIdx.x >> 5;
    const float* xr = x + (size_t)t * H_DIM;
    const float* wr = Wr + (size_t)warp * H_DIM;
    float s = 0.f;
#pragma unroll
    for (int h = lane * 4; h < H_DIM; h += 128) {
        float4 a = *(const float4*)(xr + h);
        float4 b = *(const float4*)(wr + h);
        s += a.x * b.x + a.y * b.y + a.z * b.z + a.w * b.w;
    }
#pragma unroll
    for (int o = 16; o; o >>= 1) s += __shfl_xor_sync(0xffffffffu, s, o);
    __shared__ float lg[E_NUM];
    if (lane == 0) lg[warp] = s + br[warp];
    __syncthreads();
    if (threadIdx.x == 0) {
        float mx = lg[0];
#pragma unroll
        for (int e = 1; e < E_NUM; e++) mx = fmaxf(mx, lg[e]);
        float ex[E_NUM], sum = 0.f;
#pragma unroll
        for (int e = 0; e < E_NUM; e++) { ex[e] = expf(lg[e] - mx); sum += ex[e]; }
        int i0 = 0;
#pragma unroll
        for (int e = 1; e < E_NUM; e++) if (lg[e] > lg[i0]) i0 = e;
        int i1 = (i0 == 0) ? 1 : 0;
#pragma unroll
        for (int e = 0; e < E_NUM; e++) if (e != i0 && lg[e] > lg[i1]) i1 = e;
        float inv = 1.f / sum;
        g_top_idx[2 * t + 0] = i0;  g_top_idx[2 * t + 1] = i1;
        g_top_w[2 * t + 0] = ex[i0] * inv;  g_top_w[2 * t + 1] = ex[i1] * inv;
    }
}

// ---------------- dispatch (serial, proven) ----------------------------------
__global__ void dispatch_k() {
    int e = threadIdx.x;
    if (e >= E_NUM) return;
    int c = 0;
    for (int t = 0; t < T_TOK; t++) {
        int i0 = g_top_idx[2 * t + 0];
        int i1 = g_top_idx[2 * t + 1];
        if (i0 == e)      { g_tok[e][c] = t; g_wt[e][c] = g_top_w[2 * t + 0]; c++; }
        else if (i1 == e) { g_tok[e][c] = t; g_wt[e][c] = g_top_w[2 * t + 1]; c++; }
    }
    g_cnt[e] = c;
}

// ---------------- GEMM1 (mma): act = GLU(x_e @ W1_e + b1_e) ------------------
__global__ void __launch_bounds__(256) gemm1_mma(const float* __restrict__ x,
                                                 const float* __restrict__ W1,
                                                 const float* __restrict__ b1) {
    int e = blockIdx.z;
    int cnt = g_cnt[e];
    int mB = blockIdx.y * 64;
    if (mB >= cnt) return;
    int nB = blockIdx.x * 128;

    __shared__ __align__(16) __nv_bfloat16 sAh[64 * STR];
    __shared__ __align__(16) __nv_bfloat16 sAl[64 * STR];
    __shared__ __align__(16) __nv_bfloat16 sBh[256 * STR];
    __shared__ __align__(16) __nv_bfloat16 sBl[256 * STR];
    __shared__ int toks[64];

    int tid = threadIdx.x, lane = tid & 31, wid = tid >> 5;
    int wm = wid >> 2, wn = wid & 3, g = lane >> 2, tig = lane & 3;

    if (tid < 64) toks[tid] = (mB + tid < cnt) ? g_tok[e][mB + tid] : -1;
    __syncthreads();

    const float* W1e = W1 + (size_t)e * H_DIM * 2 * I_DIM;
    int arow = tid >> 2, acol = (tid & 3) * 4;
    int t_row = toks[arow];
    const float* aptr = (t_row >= 0) ? x + (size_t)t_row * H_DIM + acol : x;
    const float* bcol = W1e + nB + (tid < 128 ? tid : (tid - 128) + I_DIM);

    uint32_t uAh = (uint32_t)__cvta_generic_to_shared(sAh);
    uint32_t uAl = (uint32_t)__cvta_generic_to_shared(sAl);
    uint32_t uBh = (uint32_t)__cvta_generic_to_shared(sBh);
    uint32_t uBl = (uint32_t)__cvta_generic_to_shared(sBl);
    int aoff = aoff_lane(lane), boff = boff_lane(lane);

    float aReg[4], bReg[BK];
    float acc[2][8][4];
#pragma unroll
    for (int a_ = 0; a_ < 2; a_++)
#pragma unroll
        for (int b_ = 0; b_ < 8; b_++)
#pragma unroll
            for (int k_ = 0; k_ < 4; k_++) acc[a_][b_][k_] = 0.f;

#define G1_LOAD(c) do {                                                         \
        int k0 = (c) * BK;                                                      \
        if (t_row >= 0) { float4 v = *(const float4*)(aptr + k0);               \
            aReg[0] = v.x; aReg[1] = v.y; aReg[2] = v.z; aReg[3] = v.w; }       \
        else { aReg[0] = aReg[1] = aReg[2] = aReg[3] = 0.f; }                   \
        _Pragma("unroll")                                                       \
        for (int k = 0; k < BK; k++)                                            \
            bReg[k] = bcol[(size_t)(k0 + k) * (2 * I_DIM)];                     \
    } while (0)

    G1_LOAD(0);
    for (int c = 0; c < H_DIM / BK; c++) {
        {
            uint32_t h0, l0, h1, l1;
            split2(aReg[0], aReg[1], h0, l0);
            split2(aReg[2], aReg[3], h1, l1);
            *(uint2*)&sAh[arow * STR + acol] = make_uint2(h0, h1);
            *(uint2*)&sAl[arow * STR + acol] = make_uint2(l0, l1);
            uint32_t hb[8], lb[8];
#pragma unroll
            for (int k = 0; k < 8; k++)
                split2(bReg[2 * k], bReg[2 * k + 1], hb[k], lb[k]);
            *(uint4*)&sBh[tid * STR + 0] = make_uint4(hb[0], hb[1], hb[2], hb[3]);
            *(uint4*)&sBh[tid * STR + 8] = make_uint4(hb[4], hb[5], hb[6], hb[7]);
            *(uint4*)&sBl[tid * STR + 0] = make_uint4(lb[0], lb[1], lb[2], lb[3]);
            *(uint4*)&sBl[tid * STR + 8] = make_uint4(lb[4], lb[5], lb[6], lb[7]);
        }
        __syncthreads();
        if (c + 1 < H_DIM / BK) G1_LOAD(c + 1);
        {
            uint32_t ah[2][4], al[2][4];
#pragma unroll
            for (int mi = 0; mi < 2; mi++) {
                uint32_t ao = (uint32_t)((wm * 32 + mi * 16) * STR + aoff) * 2;
                ldsm4(ah[mi], uAh + ao);
                ldsm4(al[mi], uAl + ao);
            }
            uint32_t bh[8][2], bl[8][2];
#pragma unroll
            for (int p = 0; p < 4; p++) {
                int nb = (p < 2) ? wn * 32 + p * 16
                                 : 128 + wn * 32 + (p - 2) * 16;
                uint32_t bo = (uint32_t)(nb * STR + boff) * 2;
                uint32_t t4[4];
                ldsm4(t4, uBh + bo);
                bh[2 * p][0] = t4[0]; bh[2 * p][1] = t4[1];
                bh[2 * p + 1][0] = t4[2]; bh[2 * p + 1][1] = t4[3];
                ldsm4(t4, uBl + bo);
                bl[2 * p][0] = t4[0]; bl[2 * p][1] = t4[1];
                bl[2 * p + 1][0] = t4[2]; bl[2 * p + 1][1] = t4[3];
            }
#pragma unroll
            for (int ni = 0; ni < 8; ni++)
#pragma unroll
                for (int mi = 0; mi < 2; mi++) {
                    mma16816(acc[mi][ni], ah[mi], bh[ni]);
                    mma16816(acc[mi][ni], al[mi], bh[ni]);
                    mma16816(acc[mi][ni], ah[mi], bl[ni]);
                }
        }
        __syncthreads();
    }

    // fused GLU epilogue -> fp32 act (proven)
#pragma unroll
    for (int mi = 0; mi < 2; mi++) {
        int m0 = mB + wm * 32 + mi * 16 + g;
#pragma unroll
        for (int ni = 0; ni < 4; ni++) {
            int j = nB + wn * 32 + ni * 8 + tig * 2;
            float bg0 = b1[(size_t)e * 2 * I_DIM + j];
            float bg1 = b1[(size_t)e * 2 * I_DIM + j + 1];
            float bu0 = b1[(size_t)e * 2 * I_DIM + I_DIM + j];
            float bu1 = b1[(size_t)e * 2 * I_DIM + I_DIM + j + 1];
#pragma unroll
            for (int h = 0; h < 2; h++) {
                int m = m0 + h * 8;
                if (m >= cnt) continue;
                float gv0 = acc[mi][ni][h * 2 + 0] + bg0;
                float gv1 = acc[mi][ni][h * 2 + 1] + bg1;
                float uv0 = acc[mi][ni + 4][h * 2 + 0] + bu0;
                float uv1 = acc[mi][ni + 4][h * 2 + 1] + bu1;
                gv0 = fminf(gv0, LIMIT);
                gv1 = fminf(gv1, LIMIT);
                uv0 = fminf(fmaxf(uv0, -LIMIT), LIMIT);
                uv1 = fminf(fmaxf(uv1, -LIMIT), LIMIT);
                float a0 = (uv0 + 1.f) * (gv0 / (1.f + __expf(-ALPHA * gv0)));
                float a1 = (uv1 + 1.f) * (gv1 / (1.f + __expf(-ALPHA * gv1)));
                float* ap = g_act + ((size_t)e * T_TOK + m) * I_DIM + j;
                ap[0] = a0;
                ap[1] = a1;
            }
        }
    }
}

// ---------------- GEMM2 (mma): out += w * (act @ W2_e + b2_e) ----------------
__global__ void __launch_bounds__(256) gemm2_mma(const float* __restrict__ W2,
                                                 const float* __restrict__ b2,
                                                 float* __restrict__ out) {
    int e = blockIdx.z;
    int cnt = g_cnt[e];
    int mB = blockIdx.y * 128;
    if (mB >= cnt) return;
    int nB = blockIdx.x * 128;

    __shared__ __align__(16) __nv_bfloat16 sAh[128 * STR];
    __shared__ __align__(16) __nv_bfloat16 sAl[128 * STR];
    __shared__ __align__(16) __nv_bfloat16 sBh[128 * STR];
    __shared__ __align__(16) __nv_bfloat16 sBl[128 * STR];
    __shared__ int toks[128];
    __shared__ float wts[128];

    int tid = threadIdx.x, lane = tid & 31, wid = tid >> 5;
    int wm = wid >> 2, wn = wid & 3, g = lane >> 2, tig = lane & 3;

    if (tid < 128) {
        int ok = (mB + tid < cnt);
        toks[tid] = ok ? g_tok[e][mB + tid] : 0;
        wts[tid]  = ok ? g_wt[e][mB + tid] : 0.f;
    }
    __syncthreads();

    const float* W2e = W2 + (size_t)e * I_DIM * H_DIM;
    const float* Ae  = g_act + (size_t)e * T_TOK * I_DIM;
    int arow = tid >> 1, acol = (tid & 1) * 8;
    bool aok = (mB + arow) < cnt;
    const float* aptr = Ae + (size_t)(mB + arow) * I_DIM + acol;
    int bn = tid & 127, bkh = (tid >> 7) * 8;
    const float* bcol = W2e + nB + bn;

    uint32_t uAh = (uint32_t)__cvta_generic_to_shared(sAh);
    uint32_t uAl = (uint32_t)__cvta_generic_to_shared(sAl);
    uint32_t uBh = (uint32_t)__cvta_generic_to_shared(sBh);
    uint32_t uBl = (uint32_t)__cvta_generic_to_shared(sBl);
    int aoff = aoff_lane(lane), boff = boff_lane(lane);

    float aReg[8], bReg[8];
    float acc[4][4][4];
#pragma unroll
    for (int a_ = 0; a_ < 4; a_++)
#pragma unroll
        for (int b_ = 0; b_ < 4; b_++)
#pragma unroll
            for (int k_ = 0; k_ < 4; k_++) acc[a_][b_][k_] = 0.f;

#define G2_LOAD(c) do {                                                         \
        int k0 = (c) * BK;                                                      \
        if (aok) {                                                              \
            float4 v0 = *(const float4*)(aptr + k0);                            \
            float4 v1 = *(const float4*)(aptr + k0 + 4);                        \
            aReg[0] = v0.x; aReg[1] = v0.y; aReg[2] = v0.z; aReg[3] = v0.w;     \
            aReg[4] = v1.x; aReg[5] = v1.y; aReg[6] = v1.z; aReg[7] = v1.w;     \
        } else {                                                                \
            _Pragma("unroll") for (int i = 0; i < 8; i++) aReg[i] = 0.f;        \
        }                                                                       \
        _Pragma("unroll")                                                       \
        for (int k = 0; k < 8; k++)                                             \
            bReg[k] = bcol[(size_t)(k0 + bkh + k) * H_DIM];                     \
    } while (0)

    G2_LOAD(0);
    for (int c = 0; c < I_DIM / BK; c++) {
        {
            uint32_t ha[4], la[4];
#pragma unroll
            for (int k = 0; k < 4; k++)
                split2(aReg[2 * k], aReg[2 * k + 1], ha[k], la[k]);
            *(uint4*)&sAh[arow * STR + acol] = make_uint4(ha[0], ha[1], ha[2], ha[3]);
            *(uint4*)&sAl[arow * STR + acol] = make_uint4(la[0], la[1], la[2], la[3]);
            uint32_t hb[4], lb[4];
#pragma unroll
            for (int k = 0; k < 4; k++)
                split2(bReg[2 * k], bReg[2 * k + 1], hb[k], lb[k]);
            *(uint4*)&sBh[bn * STR + bkh] = make_uint4(hb[0], hb[1], hb[2], hb[3]);
            *(uint4*)&sBl[bn * STR + bkh] = make_uint4(lb[0], lb[1], lb[2], lb[3]);
        }
        __syncthreads();
        if (c + 1 < I_DIM / BK) G2_LOAD(c + 1);
        {
            uint32_t ah[4][4], al[4][4];
#pragma unroll
            for (int mi = 0; mi < 4; mi++) {
                uint32_t ao = (uint32_t)((wm * 64 + mi * 16) * STR + aoff) * 2;
                ldsm4(ah[mi], uAh + ao);
                ldsm4(al[mi], uAl + ao);
            }
            uint32_t bh[4][2], bl[4][2];
#pragma unroll
            for (int p = 0; p < 2; p++) {
                uint32_t bo = (uint32_t)((wn * 32 + p * 16) * STR + boff) * 2;
                uint32_t t4[4];
                ldsm4(t4, uBh + bo);
                bh[2 * p][0] = t4[0]; bh[2 * p][1] = t4[1];
                bh[2 * p + 1][0] = t4[2]; bh[2 * p + 1][1] = t4[3];
                ldsm4(t4, uBl + bo);
                bl[2 * p][0] = t4[0]; bl[2 * p][1] = t4[1];
                bl[2 * p + 1][0] = t4[2]; bl[2 * p + 1][1] = t4[3];
            }
#pragma unroll
            for (int mi = 0; mi < 4; mi++)
#pragma unroll
                for (int ni = 0; ni < 4; ni++) {
                    mma16816(acc[mi][ni], ah[mi], bh[ni]);
                    mma16816(acc[mi][ni], al[mi], bh[ni]);
                    mma16816(acc[mi][ni], ah[mi], bl[ni]);
                }
        }
        __syncthreads();
    }

    // weighted combine epilogue (proven)
#pragma unroll
    for (int mi = 0; mi < 4; mi++) {
        int mr0 = wm * 64 + mi * 16 + g;
#pragma unroll
        for (int h = 0; h < 2; h++) {
            int mr = mr0 + h * 8;
            int m = mB + mr;
            if (m >= cnt) continue;
            int t = toks[mr];
            float w = wts[mr];
            float* op = out + (size_t)t * H_DIM;
#pragma unroll
            for (int ni = 0; ni < 4; ni++) {
                int n = nB + wn * 32 + ni * 8 + tig * 2;
                float bb0 = b2[(size_t)e * H_DIM + n];
                float bb1 = b2[(size_t)e * H_DIM + n + 1];
                atomicAdd(op + n,     w * (acc[mi][ni][h * 2 + 0] + bb0));
                atomicAdd(op + n + 1, w * (acc[mi][ni][h * 2 + 1] + bb1));
            }
        }
    }
}

// ---------------- launcher ---------------------------------------------------
extern "C" void kernel_launch(void* const* d_in, const int* in_sizes, int n_in,
                              void* d_out, int out_size) {
    const float* x  = (const float*)d_in[0];
    const float* Wr = (const float*)d_in[1];
    const float* br = (const float*)d_in[2];
    const float* W1 = (const float*)d_in[3];
    const float* b1 = (const float*)d_in[4];
    const float* W2 = (const float*)d_in[5];
    const float* b2 = (const float*)d_in[6];
    float* out = (float*)d_out;

    cudaMemsetAsync(out, 0, (size_t)out_size * sizeof(float), 0);
    router_k<<<T_TOK, 256>>>(x, Wr, br);
    dispatch_k<<<1, 32>>>();
    gemm1_mma<<<dim3(I_DIM / 128, T_TOK / 64, E_NUM), 256>>>(x, W1, b1);
    gemm2_mma<<<dim3(H_DIM / 128, T_TOK / 128, E_NUM), 256>>>(W2, b2, out);
}